// round 14
// baseline (speedup 1.0000x reference)
#include <cuda_runtime.h>

#define ROWS  8192
#define COLS  16384
#define BLOCK 512
#define NWARPS (BLOCK / 32)

// Allocation-free scratch: accumulator + completion counter.
__device__ float    g_acc   = 0.0f;
__device__ unsigned g_count = 0;

// LDG.128 non-coherent with L2 256B fetch-granularity hint.
__device__ __forceinline__ float4 ldg128_l2_256(const float4* __restrict__ a)
{
    float4 v;
    asm volatile("ld.global.nc.L2::256B.v4.f32 {%0, %1, %2, %3}, [%4];"
                 : "=f"(v.x), "=f"(v.y), "=f"(v.z), "=f"(v.w)
                 : "l"(a));
    return v;
}

__device__ __forceinline__ void epilogue(float s, float* __restrict__ out,
                                         int nblocks)
{
    // Warp reduce
    #pragma unroll
    for (int o = 16; o > 0; o >>= 1)
        s += __shfl_down_sync(0xffffffffu, s, o);

    __shared__ float ws[NWARPS];
    if ((threadIdx.x & 31) == 0) ws[threadIdx.x >> 5] = s;
    __syncthreads();

    if (threadIdx.x < 32) {
        // Warp-parallel tail: 16 partials reduced by shuffle tree.
        float t = (threadIdx.x < NWARPS) ? ws[threadIdx.x] : 0.0f;
        #pragma unroll
        for (int o = NWARPS / 2; o > 0; o >>= 1)
            t += __shfl_down_sync(0xffffffffu, t, o);

        if (threadIdx.x == 0) {
            float h = fmaxf(t - 1.0f, 0.0f);
            atomicAdd(&g_acc, h);
            // Release-ordered count increment: orders the g_acc add before
            // the counter bump without a full MEMBAR.GPU.
            unsigned done;
            asm volatile("atom.add.release.gpu.u32 %0, [%1], 1;"
                         : "=r"(done) : "l"(&g_count) : "memory");
            if (done == (unsigned)nblocks - 1u) {
                // Acquire-ordered read: all release-ordered g_acc adds visible.
                float total;
                asm volatile("ld.acquire.gpu.f32 %0, [%1];"
                             : "=f"(total) : "l"(&g_acc) : "memory");
                out[0] = total / (float)nblocks;
                // Reset for next graph replay.
                *(volatile float*)&g_acc = 0.0f;
                asm volatile("st.release.gpu.u32 [%0], 0;"
                             :: "l"(&g_count) : "memory");
            }
        }
    }
}

// One CTA per row, 512 threads, 8 fully-unrolled LDG.128 per thread with
// L2::256B hint. Warp-contiguous layout: each warp owns a contiguous 4 KB
// chunk of the row and walks it sequentially in 512 B steps, giving each
// warp-stream perfect DRAM-page sequentiality.
__global__ void __launch_bounds__(BLOCK) bloss_unrolled_kernel(
    const float* __restrict__ B, float* __restrict__ out)
{
    const int lane = threadIdx.x & 31;
    const int wid  = threadIdx.x >> 5;

    // Warp w covers float4s [w*256, (w+1)*256); load k at w*256 + k*32 + lane.
    const float4* __restrict__ p =
        reinterpret_cast<const float4*>(B + (size_t)blockIdx.x * COLS)
        + wid * 256 + lane;

    float4 v0 = ldg128_l2_256(p);
    float4 v1 = ldg128_l2_256(p + 1 * 32);
    float4 v2 = ldg128_l2_256(p + 2 * 32);
    float4 v3 = ldg128_l2_256(p + 3 * 32);
    float4 v4 = ldg128_l2_256(p + 4 * 32);
    float4 v5 = ldg128_l2_256(p + 5 * 32);
    float4 v6 = ldg128_l2_256(p + 6 * 32);
    float4 v7 = ldg128_l2_256(p + 7 * 32);

    float s0 = (v0.x + v0.y) + (v0.z + v0.w);
    float s1 = (v1.x + v1.y) + (v1.z + v1.w);
    float s2 = (v2.x + v2.y) + (v2.z + v2.w);
    float s3 = (v3.x + v3.y) + (v3.z + v3.w);
    float s4 = (v4.x + v4.y) + (v4.z + v4.w);
    float s5 = (v5.x + v5.y) + (v5.z + v5.w);
    float s6 = (v6.x + v6.y) + (v6.z + v6.w);
    float s7 = (v7.x + v7.y) + (v7.z + v7.w);

    float s = ((s0 + s1) + (s2 + s3)) + ((s4 + s5) + (s6 + s7));
    epilogue(s, out, ROWS);
}

// Generic fallback (any cols divisible by 4): one row per CTA, LDG.128 loop.
__global__ void __launch_bounds__(BLOCK) bloss_generic_kernel(
    const float* __restrict__ B, float* __restrict__ out, int cols)
{
    const float4* __restrict__ p =
        reinterpret_cast<const float4*>(B + (size_t)blockIdx.x * (size_t)cols);
    const int n4 = cols >> 2;

    float s0 = 0.0f, s1 = 0.0f, s2 = 0.0f, s3 = 0.0f;
    int i = threadIdx.x;
    for (; i + 3 * BLOCK < n4; i += 4 * BLOCK) {
        float4 v0 = p[i];
        float4 v1 = p[i + BLOCK];
        float4 v2 = p[i + 2 * BLOCK];
        float4 v3 = p[i + 3 * BLOCK];
        s0 += (v0.x + v0.y) + (v0.z + v0.w);
        s1 += (v1.x + v1.y) + (v1.z + v1.w);
        s2 += (v2.x + v2.y) + (v2.z + v2.w);
        s3 += (v3.x + v3.y) + (v3.z + v3.w);
    }
    for (; i < n4; i += BLOCK) {
        float4 v = p[i];
        s0 += (v.x + v.y) + (v.z + v.w);
    }
    epilogue((s0 + s1) + (s2 + s3), out, ROWS);
}

extern "C" void kernel_launch(void* const* d_in, const int* in_sizes, int n_in,
                              void* d_out, int out_size)
{
    const float* B = (const float*)d_in[0];
    const int rows = ROWS;                   // 8192 per problem spec
    const int cols = in_sizes[0] / rows;     // 16384

    if (cols == COLS)
        bloss_unrolled_kernel<<<rows, BLOCK>>>(B, (float*)d_out);
    else
        bloss_generic_kernel<<<rows, BLOCK>>>(B, (float*)d_out, cols);
}

// round 15
// speedup vs baseline: 1.0167x; 1.0167x over previous
#include <cuda_runtime.h>

#define ROWS  8192
#define COLS  16384
#define BLOCK 512
#define NWARPS (BLOCK / 32)

// Allocation-free scratch: accumulator + completion counter.
__device__ float    g_acc   = 0.0f;
__device__ unsigned g_count = 0;

// LDG.128 non-coherent with L2 256B fetch-granularity hint (best measured
// config: halves LTS transactions per byte on a sequential stream).
__device__ __forceinline__ float4 ldg128_l2_256(const float4* __restrict__ a)
{
    float4 v;
    asm volatile("ld.global.nc.L2::256B.v4.f32 {%0, %1, %2, %3}, [%4];"
                 : "=f"(v.x), "=f"(v.y), "=f"(v.z), "=f"(v.w)
                 : "l"(a));
    return v;
}

__device__ __forceinline__ void epilogue(float s, float* __restrict__ out,
                                         int nblocks)
{
    // Warp reduce
    #pragma unroll
    for (int o = 16; o > 0; o >>= 1)
        s += __shfl_down_sync(0xffffffffu, s, o);

    __shared__ float ws[NWARPS];
    if ((threadIdx.x & 31) == 0) ws[threadIdx.x >> 5] = s;
    __syncthreads();

    if (threadIdx.x < 32) {
        // Warp-parallel tail: 16 partials reduced by shuffle tree.
        float t = (threadIdx.x < NWARPS) ? ws[threadIdx.x] : 0.0f;
        #pragma unroll
        for (int o = NWARPS / 2; o > 0; o >>= 1)
            t += __shfl_down_sync(0xffffffffu, t, o);

        if (threadIdx.x == 0) {
            float h = fmaxf(t - 1.0f, 0.0f);
            atomicAdd(&g_acc, h);
            // Release-ordered count increment: orders the g_acc add before
            // the counter bump without a full MEMBAR.GPU.
            unsigned done;
            asm volatile("atom.add.release.gpu.u32 %0, [%1], 1;"
                         : "=r"(done) : "l"(&g_count) : "memory");
            if (done == (unsigned)nblocks - 1u) {
                // Acquire-ordered read: all release-ordered g_acc adds visible.
                float total;
                asm volatile("ld.acquire.gpu.f32 %0, [%1];"
                             : "=f"(total) : "l"(&g_acc) : "memory");
                out[0] = total / (float)nblocks;
                // Reset for next graph replay.
                *(volatile float*)&g_acc = 0.0f;
                asm volatile("st.release.gpu.u32 [%0], 0;"
                             :: "l"(&g_count) : "memory");
            }
        }
    }
}

// FINAL config (R11): one CTA per row, 512 threads, lane-major 8-deep fully
// unrolled LDG.128 with L2::256B fetch-granularity hint. Measured at the
// chip's path-independent LTS fabric ceiling (~7.0 TB/s, 88.8% DRAM-active);
// all SM-side resources (issue, occupancy, MLP) verified slack. Falsified
// alternatives: __ldcs, L1::no_allocate, LDG.256, warp-contiguous layout,
// 256-thread CTAs, warp-per-row, multi-row CTAs, unfused two-kernel split.
__global__ void __launch_bounds__(BLOCK) bloss_unrolled_kernel(
    const float* __restrict__ B, float* __restrict__ out)
{
    const float4* __restrict__ p =
        reinterpret_cast<const float4*>(B + (size_t)blockIdx.x * COLS)
        + threadIdx.x;

    float4 v0 = ldg128_l2_256(p);
    float4 v1 = ldg128_l2_256(p + 1 * BLOCK);
    float4 v2 = ldg128_l2_256(p + 2 * BLOCK);
    float4 v3 = ldg128_l2_256(p + 3 * BLOCK);
    float4 v4 = ldg128_l2_256(p + 4 * BLOCK);
    float4 v5 = ldg128_l2_256(p + 5 * BLOCK);
    float4 v6 = ldg128_l2_256(p + 6 * BLOCK);
    float4 v7 = ldg128_l2_256(p + 7 * BLOCK);

    float s0 = (v0.x + v0.y) + (v0.z + v0.w);
    float s1 = (v1.x + v1.y) + (v1.z + v1.w);
    float s2 = (v2.x + v2.y) + (v2.z + v2.w);
    float s3 = (v3.x + v3.y) + (v3.z + v3.w);
    float s4 = (v4.x + v4.y) + (v4.z + v4.w);
    float s5 = (v5.x + v5.y) + (v5.z + v5.w);
    float s6 = (v6.x + v6.y) + (v6.z + v6.w);
    float s7 = (v7.x + v7.y) + (v7.z + v7.w);

    float s = ((s0 + s1) + (s2 + s3)) + ((s4 + s5) + (s6 + s7));
    epilogue(s, out, ROWS);
}

// Generic fallback (any cols divisible by 4): one row per CTA, LDG.128 loop.
__global__ void __launch_bounds__(BLOCK) bloss_generic_kernel(
    const float* __restrict__ B, float* __restrict__ out, int cols)
{
    const float4* __restrict__ p =
        reinterpret_cast<const float4*>(B + (size_t)blockIdx.x * (size_t)cols);
    const int n4 = cols >> 2;

    float s0 = 0.0f, s1 = 0.0f, s2 = 0.0f, s3 = 0.0f;
    int i = threadIdx.x;
    for (; i + 3 * BLOCK < n4; i += 4 * BLOCK) {
        float4 v0 = p[i];
        float4 v1 = p[i + BLOCK];
        float4 v2 = p[i + 2 * BLOCK];
        float4 v3 = p[i + 3 * BLOCK];
        s0 += (v0.x + v0.y) + (v0.z + v0.w);
        s1 += (v1.x + v1.y) + (v1.z + v1.w);
        s2 += (v2.x + v2.y) + (v2.z + v2.w);
        s3 += (v3.x + v3.y) + (v3.z + v3.w);
    }
    for (; i < n4; i += BLOCK) {
        float4 v = p[i];
        s0 += (v.x + v.y) + (v.z + v.w);
    }
    epilogue((s0 + s1) + (s2 + s3), out, ROWS);
}

extern "C" void kernel_launch(void* const* d_in, const int* in_sizes, int n_in,
                              void* d_out, int out_size)
{
    const float* B = (const float*)d_in[0];
    const int rows = ROWS;                   // 8192 per problem spec
    const int cols = in_sizes[0] / rows;     // 16384

    if (cols == COLS)
        bloss_unrolled_kernel<<<rows, BLOCK>>>(B, (float*)d_out);
    else
        bloss_generic_kernel<<<rows, BLOCK>>>(B, (float*)d_out, cols);
}

// round 16
// speedup vs baseline: 1.0200x; 1.0033x over previous
#include <cuda_runtime.h>

#define ROWS  8192
#define COLS  16384
#define BLOCK 512
#define NWARPS (BLOCK / 32)

// Allocation-free scratch: accumulator + completion counter.
__device__ float    g_acc   = 0.0f;
__device__ unsigned g_count = 0;

// LDG.128 non-coherent with L2 256B fetch-granularity hint (best measured
// config: halves LTS transactions per byte on a sequential stream).
__device__ __forceinline__ float4 ldg128_l2_256(const float4* __restrict__ a)
{
    float4 v;
    asm volatile("ld.global.nc.L2::256B.v4.f32 {%0, %1, %2, %3}, [%4];"
                 : "=f"(v.x), "=f"(v.y), "=f"(v.z), "=f"(v.w)
                 : "l"(a));
    return v;
}

__device__ __forceinline__ void epilogue(float s, float* __restrict__ out,
                                         int nblocks)
{
    // Warp reduce
    #pragma unroll
    for (int o = 16; o > 0; o >>= 1)
        s += __shfl_down_sync(0xffffffffu, s, o);

    __shared__ float ws[NWARPS];
    if ((threadIdx.x & 31) == 0) ws[threadIdx.x >> 5] = s;
    __syncthreads();

    if (threadIdx.x < 32) {
        // Warp-parallel tail: 16 partials reduced by shuffle tree.
        float t = (threadIdx.x < NWARPS) ? ws[threadIdx.x] : 0.0f;
        #pragma unroll
        for (int o = NWARPS / 2; o > 0; o >>= 1)
            t += __shfl_down_sync(0xffffffffu, t, o);

        if (threadIdx.x == 0) {
            float h = fmaxf(t - 1.0f, 0.0f);
            atomicAdd(&g_acc, h);
            // Release-ordered count increment: orders the g_acc add before
            // the counter bump without a full MEMBAR.GPU.
            unsigned done;
            asm volatile("atom.add.release.gpu.u32 %0, [%1], 1;"
                         : "=r"(done) : "l"(&g_count) : "memory");
            if (done == (unsigned)nblocks - 1u) {
                // Acquire-ordered read: all release-ordered g_acc adds visible.
                float total;
                asm volatile("ld.acquire.gpu.f32 %0, [%1];"
                             : "=f"(total) : "l"(&g_acc) : "memory");
                out[0] = total / (float)nblocks;
                // Reset for next graph replay.
                *(volatile float*)&g_acc = 0.0f;
                asm volatile("st.release.gpu.u32 [%0], 0;"
                             :: "l"(&g_count) : "memory");
            }
        }
    }
}

// FINAL config: one CTA per row, 512 threads, lane-major 8-deep fully
// unrolled LDG.128 with L2::256B fetch-granularity hint. Reproducibly at
// the chip's path-independent LTS fabric ceiling (~7.0 TB/s, 87-89%
// DRAM-active across 4 runs); SM-side resources (issue 9.8%, occ 74%,
// outstanding-load budget 13x over requirement) all verified slack.
// Falsified alternatives: __ldcs, L1::no_allocate, LDG.256 (occ loss),
// warp-contiguous layout, 256-thread CTAs, warp-per-row, 4-rows-per-CTA,
// unfused two-kernel split, __threadfence epilogue.
__global__ void __launch_bounds__(BLOCK) bloss_unrolled_kernel(
    const float* __restrict__ B, float* __restrict__ out)
{
    const float4* __restrict__ p =
        reinterpret_cast<const float4*>(B + (size_t)blockIdx.x * COLS)
        + threadIdx.x;

    float4 v0 = ldg128_l2_256(p);
    float4 v1 = ldg128_l2_256(p + 1 * BLOCK);
    float4 v2 = ldg128_l2_256(p + 2 * BLOCK);
    float4 v3 = ldg128_l2_256(p + 3 * BLOCK);
    float4 v4 = ldg128_l2_256(p + 4 * BLOCK);
    float4 v5 = ldg128_l2_256(p + 5 * BLOCK);
    float4 v6 = ldg128_l2_256(p + 6 * BLOCK);
    float4 v7 = ldg128_l2_256(p + 7 * BLOCK);

    float s0 = (v0.x + v0.y) + (v0.z + v0.w);
    float s1 = (v1.x + v1.y) + (v1.z + v1.w);
    float s2 = (v2.x + v2.y) + (v2.z + v2.w);
    float s3 = (v3.x + v3.y) + (v3.z + v3.w);
    float s4 = (v4.x + v4.y) + (v4.z + v4.w);
    float s5 = (v5.x + v5.y) + (v5.z + v5.w);
    float s6 = (v6.x + v6.y) + (v6.z + v6.w);
    float s7 = (v7.x + v7.y) + (v7.z + v7.w);

    float s = ((s0 + s1) + (s2 + s3)) + ((s4 + s5) + (s6 + s7));
    epilogue(s, out, ROWS);
}

// Generic fallback (any cols divisible by 4): one row per CTA, LDG.128 loop.
__global__ void __launch_bounds__(BLOCK) bloss_generic_kernel(
    const float* __restrict__ B, float* __restrict__ out, int cols)
{
    const float4* __restrict__ p =
        reinterpret_cast<const float4*>(B + (size_t)blockIdx.x * (size_t)cols);
    const int n4 = cols >> 2;

    float s0 = 0.0f, s1 = 0.0f, s2 = 0.0f, s3 = 0.0f;
    int i = threadIdx.x;
    for (; i + 3 * BLOCK < n4; i += 4 * BLOCK) {
        float4 v0 = p[i];
        float4 v1 = p[i + BLOCK];
        float4 v2 = p[i + 2 * BLOCK];
        float4 v3 = p[i + 3 * BLOCK];
        s0 += (v0.x + v0.y) + (v0.z + v0.w);
        s1 += (v1.x + v1.y) + (v1.z + v1.w);
        s2 += (v2.x + v2.y) + (v2.z + v2.w);
        s3 += (v3.x + v3.y) + (v3.z + v3.w);
    }
    for (; i < n4; i += BLOCK) {
        float4 v = p[i];
        s0 += (v.x + v.y) + (v.z + v.w);
    }
    epilogue((s0 + s1) + (s2 + s3), out, ROWS);
}

extern "C" void kernel_launch(void* const* d_in, const int* in_sizes, int n_in,
                              void* d_out, int out_size)
{
    const float* B = (const float*)d_in[0];
    const int rows = ROWS;                   // 8192 per problem spec
    const int cols = in_sizes[0] / rows;     // 16384

    if (cols == COLS)
        bloss_unrolled_kernel<<<rows, BLOCK>>>(B, (float*)d_out);
    else
        bloss_generic_kernel<<<rows, BLOCK>>>(B, (float*)d_out, cols);
}